// round 10
// baseline (speedup 1.0000x reference)
#include <cuda_runtime.h>
#include <cuda_bf16.h>
#include <mma.h>
#include <cstdint>
#include <cstddef>

using namespace nvcuda;

#define NV       50000
#define NT       10
#define NE       4
#define NH       256
#define NM       100000
#define BIGNEG   1.0e7f

#define EPI_NONE  0
#define EPI_GATES 1
#define EPI_HOUT  2

// ---------------- device scratch (static, no allocs) ----------------
__device__ float g_h  [(size_t)NV * NH];
__device__ float g_s0 [(size_t)NV * NH];
__device__ float g_s1 [(size_t)NV * NH];
__device__ float g_msg[(size_t)NV * NH];
__device__ float g_rh [(size_t)NV * NH];
__device__ float g_u  [(size_t)NV * NH];
__device__ float g_emb[(size_t)NV * NH];
__device__ float g_T  [(size_t)NV * 2048];

// ---------------- GEMM: C[MxN] = concat_parts(A)[MxK] @ B[KxN] (+bias) ----
// A: up to 8 parts, each [M x 256] row-major, own row stride; boundaries at
// k multiples of 256. bf16x3 split, fp32 accumulate.
// bgroup: B is [K=256] x 8 groups of 256 cols, group-major (edge_w layout).
// epi: fused GRU epilogues (see EPI_*).
struct AParts { const float* p[8]; int ld[8]; };

__global__ __launch_bounds__(256, 3)
void gemm_bf16x3(AParts parts, const float* __restrict__ B,
                 float* __restrict__ C, const float* __restrict__ bias,
                 int M, int N, int K, int bgroup, int epi,
                 float* __restrict__ aux_h, float* __restrict__ aux_rh,
                 float* __restrict__ aux_u)
{
    constexpr int BM = 128, BN = 128, BK = 16;
    constexpr int LDA = BK + 8;    // 24 (bf16 elems)
    constexpr int LDB = BN + 8;    // 136
    constexpr int LDS = 64 + 4;    // 68 (floats, epilogue staging)

    constexpr int AH_N = 2 * BM * LDA;     // 6144
    constexpr int BH_N = 2 * BK * LDB;     // 4352
    __shared__ __align__(16) char smraw[(2 * AH_N + 2 * BH_N) * 2];
    __nv_bfloat16* Ah = (__nv_bfloat16*)smraw;
    __nv_bfloat16* Al = Ah + AH_N;
    __nv_bfloat16* Bh = Al + AH_N;
    __nv_bfloat16* Bl = Bh + BH_N;
    float* stage = (float*)smraw;

    const int bm0 = blockIdx.y * BM;
    const int bn0 = blockIdx.x * BN;
    const int tid = threadIdx.x;
    const int wid = tid >> 5;
    const int warp_m = wid >> 1;
    const int warp_n = wid & 1;

    const int arow = tid >> 2;
    const int acol = (tid & 3) * 4;
    const int brow = tid >> 5;
    const int bcol = (tid & 31) * 4;

    // B addressing (grouped: 256-col blocks with 65536-element group stride)
    const float* Bp;
    int ldB;
    if (bgroup) { Bp = B + (size_t)(bn0 >> 8) * 65536 + (bn0 & 255); ldB = 256; }
    else        { Bp = B + bn0; ldB = N; }

    wmma::fragment<wmma::accumulator, 16, 16, 16, float> acc[2][4];
#pragma unroll
    for (int i = 0; i < 2; i++)
#pragma unroll
        for (int j = 0; j < 4; j++) wmma::fill_fragment(acc[i][j], 0.f);

    const int nk = K >> 4;

    auto split4 = [](float4 v, __nv_bfloat16* hi, __nv_bfloat16* lo) {
        float f[4] = { v.x, v.y, v.z, v.w };
#pragma unroll
        for (int i = 0; i < 4; i++) {
            __nv_bfloat16 h = __float2bfloat16(f[i]);
            hi[i] = h;
            lo[i] = __float2bfloat16(f[i] - __bfloat162float(h));
        }
    };

    auto loadTile = [&](int kt, int buf) {
        const int gk0 = kt << 4;
        const int pi  = gk0 >> 8;
        const float* Ap = parts.p[pi];
        const int lda   = parts.ld[pi];
        const int kin   = gk0 & 255;
        __nv_bfloat16 hi[4], lo[4];
#pragma unroll
        for (int pp = 0; pp < 2; ++pp) {
            int r = arow + pp * 64;
            int grow = bm0 + r;
            float4 v = make_float4(0.f, 0.f, 0.f, 0.f);
            if (grow < M) v = *(const float4*)(Ap + (size_t)grow * lda + kin + acol);
            split4(v, hi, lo);
            int o = buf * BM * LDA + r * LDA + acol;
#pragma unroll
            for (int i = 0; i < 4; i++) { Ah[o + i] = hi[i]; Al[o + i] = lo[i]; }
        }
#pragma unroll
        for (int pp = 0; pp < 2; ++pp) {
            int r = brow + pp * 8;
            float4 v = *(const float4*)(Bp + (size_t)(gk0 + r) * ldB + bcol);
            split4(v, hi, lo);
            int o = buf * BK * LDB + r * LDB + bcol;
#pragma unroll
            for (int i = 0; i < 4; i++) { Bh[o + i] = hi[i]; Bl[o + i] = lo[i]; }
        }
    };

    loadTile(0, 0);
    __syncthreads();

    for (int kt = 0; kt < nk; ++kt) {
        int buf = kt & 1;
        if (kt + 1 < nk) loadTile(kt + 1, buf ^ 1);
        const __nv_bfloat16* Ahb = Ah + buf * BM * LDA;
        const __nv_bfloat16* Alb = Al + buf * BM * LDA;
        const __nv_bfloat16* Bhb = Bh + buf * BK * LDB;
        const __nv_bfloat16* Blb = Bl + buf * BK * LDB;

        // Term-wise schedule: B fragments (bb) are reused in place so peak live
        // fragment registers drop 48 -> 32, enabling 3 CTAs/SM.
        wmma::fragment<wmma::matrix_a, 16, 16, 16, __nv_bfloat16, wmma::row_major> ah[2], a2[2];
        wmma::fragment<wmma::matrix_b, 16, 16, 16, __nv_bfloat16, wmma::row_major> bb[4];

#pragma unroll
        for (int i = 0; i < 2; i++)
            wmma::load_matrix_sync(ah[i], Ahb + (warp_m * 32 + i * 16) * LDA, LDA);
#pragma unroll
        for (int j = 0; j < 4; j++)
            wmma::load_matrix_sync(bb[j], Bhb + warp_n * 64 + j * 16, LDB);
#pragma unroll
        for (int i = 0; i < 2; i++)
#pragma unroll
            for (int j = 0; j < 4; j++)
                wmma::mma_sync(acc[i][j], ah[i], bb[j], acc[i][j]);   // ah*bh

#pragma unroll
        for (int i = 0; i < 2; i++)
            wmma::load_matrix_sync(a2[i], Alb + (warp_m * 32 + i * 16) * LDA, LDA);
#pragma unroll
        for (int i = 0; i < 2; i++)
#pragma unroll
            for (int j = 0; j < 4; j++)
                wmma::mma_sync(acc[i][j], a2[i], bb[j], acc[i][j]);   // al*bh

#pragma unroll
        for (int j = 0; j < 4; j++)
            wmma::load_matrix_sync(bb[j], Blb + warp_n * 64 + j * 16, LDB);
#pragma unroll
        for (int i = 0; i < 2; i++)
#pragma unroll
            for (int j = 0; j < 4; j++)
                wmma::mma_sync(acc[i][j], ah[i], bb[j], acc[i][j]);   // ah*bl

        __syncthreads();
    }

    // Epilogue: two N-halves through smem staging; fused bias + GRU math.
    const int col4 = (tid & 15) * 4;
    const int r0   = tid >> 4;
#pragma unroll
    for (int half = 0; half < 2; ++half) {
        if (warp_n == half) {
#pragma unroll
            for (int i = 0; i < 2; i++)
#pragma unroll
                for (int j = 0; j < 4; j++)
                    wmma::store_matrix_sync(stage + (warp_m * 32 + i * 16) * LDS + j * 16,
                                            acc[i][j], LDS, wmma::mem_row_major);
        }
        __syncthreads();
#pragma unroll
        for (int rr = 0; rr < 8; ++rr) {
            int r = r0 + rr * 16;
            int m = bm0 + r;
            if (m < M) {
                float4 v = *(float4*)(stage + r * LDS + col4);
                int n = bn0 + half * 64 + col4;
                if (bias) {
                    v.x += bias[n + 0]; v.y += bias[n + 1];
                    v.z += bias[n + 2]; v.w += bias[n + 3];
                }
                if (epi == EPI_NONE) {
                    *(float4*)(C + (size_t)m * N + n) = v;
                } else if (epi == EPI_GATES) {
                    // n < 256: rh = sigmoid(v) * h ; n >= 256: u = sigmoid(v)
                    float s[4] = { v.x, v.y, v.z, v.w };
#pragma unroll
                    for (int q = 0; q < 4; q++) s[q] = 1.f / (1.f + expf(-s[q]));
                    if (n < 256) {
                        float4 hh = *(const float4*)(aux_h + (size_t)m * 256 + n);
                        float4 o;
                        o.x = s[0] * hh.x; o.y = s[1] * hh.y;
                        o.z = s[2] * hh.z; o.w = s[3] * hh.w;
                        *(float4*)(aux_rh + (size_t)m * 256 + n) = o;
                    } else {
                        float4 o; o.x = s[0]; o.y = s[1]; o.z = s[2]; o.w = s[3];
                        *(float4*)(aux_u + (size_t)m * 256 + (n - 256)) = o;
                    }
                } else {  // EPI_HOUT: h = u*h + (1-u)*tanh(v)
                    float4 uu = *(const float4*)(aux_u + (size_t)m * 256 + n);
                    float4 hh = *(const float4*)(aux_h + (size_t)m * 256 + n);
                    float4 o;
                    o.x = uu.x * hh.x + (1.f - uu.x) * tanhf(v.x);
                    o.y = uu.y * hh.y + (1.f - uu.y) * tanhf(v.y);
                    o.z = uu.z * hh.z + (1.f - uu.z) * tanhf(v.z);
                    o.w = uu.w * hh.w + (1.f - uu.w) * tanhf(v.w);
                    *(float4*)(aux_h + (size_t)m * 256 + n) = o;
                }
            }
        }
        __syncthreads();
    }
}

// ---------------- transform-first edge aggregation ----------------
// msg[tgt] += T[src, e-block];  msg[src] += T[tgt, (4+e)-block]
__global__ void scatter_kernel(const int* __restrict__ adj,
                               const float* __restrict__ T, float* __restrict__ msg)
{
    int unit = blockIdx.x * 4 + (threadIdx.x >> 6);
    if (unit >= NE * NM) return;
    int e = unit / NM;
    int m = unit - e * NM;
    int lane = threadIdx.x & 63;
    const int* ap = adj + ((size_t)e * NM + m) * 2;
    int src = __ldg(ap + 0);
    int tgt = __ldg(ap + 1);
    float4 a = *(const float4*)(T + (size_t)src * 2048 + e * 256 + lane * 4);
    float* d0 = msg + (size_t)tgt * NH + lane * 4;
    asm volatile("red.global.add.v4.f32 [%0], {%1,%2,%3,%4};"
                 :: "l"(d0), "f"(a.x), "f"(a.y), "f"(a.z), "f"(a.w) : "memory");
    float4 b = *(const float4*)(T + (size_t)tgt * 2048 + (4 + e) * 256 + lane * 4);
    float* d1 = msg + (size_t)src * NH + lane * 4;
    asm volatile("red.global.add.v4.f32 [%0], {%1,%2,%3,%4};"
                 :: "l"(d1), "f"(b.x), "f"(b.y), "f"(b.z), "f"(b.w) : "memory");
}

// ---------------- embedding: emb[v] = [label_e(128) | max_t type_e(128)] ----
__global__ void embed_kernel(const int* __restrict__ lab_ids, const int* __restrict__ typ_ids,
                             const float* __restrict__ typ_mask,
                             const float* __restrict__ lab_tab, const float* __restrict__ typ_tab,
                             float* __restrict__ emb)
{
    int v = blockIdx.x;
    int f = threadIdx.x;
    float val;
    if (f < 128) {
        val = lab_tab[(size_t)__ldg(&lab_ids[v]) * 128 + f];
    } else {
        int ff = f - 128;
        float mx = -3.4e38f;
        for (int t = 0; t < NT; ++t) {
            int ti = __ldg(&typ_ids[v * NT + t]);
            float mk = __ldg(&typ_mask[v * NT + t]);
            float e = typ_tab[(size_t)ti * 128 + ff] + (1.0f - mk) * (-BIGNEG);
            mx = fmaxf(mx, e);
        }
        val = mx;
    }
    emb[(size_t)v * 256 + f] = val;
}

// ---------------- host ----------------
static void* symaddr(const void* sym)
{
    void* p = nullptr;
    cudaGetSymbolAddress(&p, sym);
    return p;
}

static void launch_gemm(const float* const* partp, const int* partld, int nparts,
                        const float* B, float* C, const float* bias, int M, int N,
                        int bgroup, int epi, float* ah, float* arh, float* au)
{
    AParts ap;
    for (int i = 0; i < 8; ++i) {
        ap.p[i]  = (i < nparts) ? partp[i]  : nullptr;
        ap.ld[i] = (i < nparts) ? partld[i] : 0;
    }
    int K = nparts * 256;
    dim3 grid(N / 128, (M + 127) / 128);
    gemm_bf16x3<<<grid, 256>>>(ap, B, C, bias, M, N, K, bgroup, epi, ah, arh, au);
}

extern "C" void kernel_launch(void* const* d_in, const int* in_sizes, int n_in,
                              void* d_out, int out_size)
{
    const int*   lab_ids  = (const int*)  d_in[0];
    const int*   typ_ids  = (const int*)  d_in[1];
    const float* typ_mask = (const float*)d_in[2];
    const int*   adj      = (const int*)  d_in[3];
    const float* lab_tab  = (const float*)d_in[4];
    const float* typ_tab  = (const float*)d_in[5];
    const float* w_init   = (const float*)d_in[6];
    const float* edge_w   = (const float*)d_in[7];
    const float *wg[4], *bg[4], *wc[4], *bc[4];
    for (int l = 0; l < 4; ++l) {
        wg[l] = (const float*)d_in[8 + 4 * l];
        bg[l] = (const float*)d_in[9 + 4 * l];
        wc[l] = (const float*)d_in[10 + 4 * l];
        bc[l] = (const float*)d_in[11 + 4 * l];
    }

    float* h    = (float*)symaddr(g_h);
    float* s0   = (float*)symaddr(g_s0);
    float* s1   = (float*)symaddr(g_s1);
    float* msg  = (float*)symaddr(g_msg);
    float* rh   = (float*)symaddr(g_rh);
    float* u    = (float*)symaddr(g_u);
    float* emb  = (float*)symaddr(g_emb);
    float* T    = (float*)symaddr(g_T);

    const int steps[4] = {3, 1, 3, 1};
    const size_t VH_BYTES = (size_t)NV * NH * sizeof(float);

    // ---- embed + init projection ----
    embed_kernel<<<NV, 256>>>(lab_ids, typ_ids, typ_mask, lab_tab, typ_tab, emb);
    {
        const float* pp[1] = { emb }; int pl[1] = { 256 };
        launch_gemm(pp, pl, 1, w_init, h, nullptr, NV, 256, 0, EPI_NONE,
                    nullptr, nullptr, nullptr);
    }
    cudaMemcpyAsync(s0, h, VH_BYTES, cudaMemcpyDeviceToDevice, 0);

    for (int l = 0; l < 4; ++l) {
        for (int st = 0; st < steps[l]; ++st) {
            // ---- T = h @ edge_w[l] (grouped B, N=2048) ----
            {
                const float* pp[1] = { h }; int pl[1] = { 256 };
                launch_gemm(pp, pl, 1, edge_w + (size_t)l * 8 * NH * NH,
                            T, nullptr, NV, 2048, 1, EPI_NONE,
                            nullptr, nullptr, nullptr);
            }
            // ---- msg = scatter-add of T rows (L2-resident atomics) ----
            cudaMemsetAsync(msg, 0, VH_BYTES, 0);
            scatter_kernel<<<(NE * NM + 3) / 4, 256>>>(adj, T, msg);

            // ---- parts: x = [res..., msg] ----
            const float* px[4]; int nx;
            if (l == 0 || l == 2) { px[0] = msg; nx = 1; }
            else if (l == 1)      { px[0] = s0; px[1] = msg; nx = 2; }
            else                  { px[0] = s0; px[1] = s1; px[2] = msg; nx = 3; }

            // ---- gates: sigmoid([x,h]@wg + bg) -> rh, u (fused epilogue) ----
            {
                const float* pp[4]; int pl[4];
                for (int i = 0; i < nx; ++i) { pp[i] = px[i]; pl[i] = 256; }
                pp[nx] = h; pl[nx] = 256;
                launch_gemm(pp, pl, nx + 1, wg[l], nullptr, bg[l], NV, 512, 0,
                            EPI_GATES, h, rh, u);
            }

            // ---- h = u*h + (1-u)*tanh([x,rh]@wc + bc) (fused epilogue) ----
            {
                const float* pp[4]; int pl[4];
                for (int i = 0; i < nx; ++i) { pp[i] = px[i]; pl[i] = 256; }
                pp[nx] = rh; pl[nx] = 256;
                launch_gemm(pp, pl, nx + 1, wc[l], nullptr, bc[l], NV, 256, 0,
                            EPI_HOUT, h, nullptr, u);
            }
        }
        if (l == 0) cudaMemcpyAsync(s1, h, VH_BYTES, cudaMemcpyDeviceToDevice, 0);
    }

    cudaMemcpyAsync(d_out, h, VH_BYTES, cudaMemcpyDeviceToDevice, 0);
}

// round 12
// speedup vs baseline: 1.6886x; 1.6886x over previous
#include <cuda_runtime.h>
#include <cuda_bf16.h>
#include <mma.h>
#include <cstdint>
#include <cstddef>

using namespace nvcuda;

#define NV       50000
#define NT       10
#define NE       4
#define NH       256
#define NM       100000
#define BIGNEG   1.0e7f

#define EPI_NONE  0
#define EPI_GATES 1
#define EPI_HOUT  2

// ---------------- device scratch (static, no allocs) ----------------
__device__ float g_h  [(size_t)NV * NH];
__device__ float g_s0 [(size_t)NV * NH];
__device__ float g_s1 [(size_t)NV * NH];
__device__ float g_msg[(size_t)NV * NH];
__device__ float g_rh [(size_t)NV * NH];
__device__ float g_u  [(size_t)NV * NH];
__device__ float g_emb[(size_t)NV * NH];
__device__ float g_T  [(size_t)NV * 2048];

// ---------------- GEMM: C[MxN] = concat_parts(A)[MxK] @ B[KxN] (+bias) ----
// A: up to 8 parts, each [M x 256] row-major, own row stride; boundaries at
// k multiples of 256. bf16x3 split, fp32 accumulate.
// bgroup: B is [K=256] x 8 groups of 256 cols, group-major (edge_w layout).
// epi: fused GRU epilogues (see EPI_*).
// Pipelined: global->reg prefetch at loop top, MMAs cover the load latency,
// reg->smem split/store afterwards, then barrier.
struct AParts { const float* p[8]; int ld[8]; };

__global__ __launch_bounds__(256)
void gemm_bf16x3(AParts parts, const float* __restrict__ B,
                 float* __restrict__ C, const float* __restrict__ bias,
                 int M, int N, int K, int bgroup, int epi,
                 float* __restrict__ aux_h, float* __restrict__ aux_rh,
                 float* __restrict__ aux_u)
{
    constexpr int BM = 128, BN = 128, BK = 16;
    constexpr int LDA = BK + 8;    // 24 (bf16 elems)
    constexpr int LDB = BN + 8;    // 136
    constexpr int LDS = 64 + 4;    // 68 (floats, epilogue staging)

    constexpr int AH_N = 2 * BM * LDA;     // 6144
    constexpr int BH_N = 2 * BK * LDB;     // 4352
    __shared__ __align__(16) char smraw[(2 * AH_N + 2 * BH_N) * 2];
    __nv_bfloat16* Ah = (__nv_bfloat16*)smraw;
    __nv_bfloat16* Al = Ah + AH_N;
    __nv_bfloat16* Bh = Al + AH_N;
    __nv_bfloat16* Bl = Bh + BH_N;
    float* stage = (float*)smraw;

    const int bm0 = blockIdx.y * BM;
    const int bn0 = blockIdx.x * BN;
    const int tid = threadIdx.x;
    const int wid = tid >> 5;
    const int warp_m = wid >> 1;
    const int warp_n = wid & 1;

    const int arow = tid >> 2;
    const int acol = (tid & 3) * 4;
    const int brow = tid >> 5;
    const int bcol = (tid & 31) * 4;

    // B addressing (grouped: 256-col blocks with 65536-element group stride)
    const float* Bp;
    int ldB;
    if (bgroup) { Bp = B + (size_t)(bn0 >> 8) * 65536 + (bn0 & 255); ldB = 256; }
    else        { Bp = B + bn0; ldB = N; }

    wmma::fragment<wmma::accumulator, 16, 16, 16, float> acc[2][4];
#pragma unroll
    for (int i = 0; i < 2; i++)
#pragma unroll
        for (int j = 0; j < 4; j++) wmma::fill_fragment(acc[i][j], 0.f);

    const int nk = K >> 4;

    auto split4 = [](float4 v, __nv_bfloat16* hi, __nv_bfloat16* lo) {
        float f[4] = { v.x, v.y, v.z, v.w };
#pragma unroll
        for (int i = 0; i < 4; i++) {
            __nv_bfloat16 h = __float2bfloat16(f[i]);
            hi[i] = h;
            lo[i] = __float2bfloat16(f[i] - __bfloat162float(h));
        }
    };

    // ---- pipeline registers (global prefetch) ----
    float4 ra[2], rb[2];

    auto loadG = [&](int kt) {
        const int gk0 = kt << 4;
        const int pi  = gk0 >> 8;
        const float* Ap = parts.p[pi];
        const int lda   = parts.ld[pi];
        const int kin   = gk0 & 255;
#pragma unroll
        for (int pp = 0; pp < 2; ++pp) {
            int grow = bm0 + arow + pp * 64;
            ra[pp] = make_float4(0.f, 0.f, 0.f, 0.f);
            if (grow < M) ra[pp] = *(const float4*)(Ap + (size_t)grow * lda + kin + acol);
        }
#pragma unroll
        for (int pp = 0; pp < 2; ++pp) {
            int r = brow + pp * 8;
            rb[pp] = *(const float4*)(Bp + (size_t)(gk0 + r) * ldB + bcol);
        }
    };

    auto storeS = [&](int buf) {
        __nv_bfloat16 hi[4], lo[4];
#pragma unroll
        for (int pp = 0; pp < 2; ++pp) {
            int r = arow + pp * 64;
            split4(ra[pp], hi, lo);
            int o = buf * BM * LDA + r * LDA + acol;
#pragma unroll
            for (int i = 0; i < 4; i++) { Ah[o + i] = hi[i]; Al[o + i] = lo[i]; }
        }
#pragma unroll
        for (int pp = 0; pp < 2; ++pp) {
            int r = brow + pp * 8;
            split4(rb[pp], hi, lo);
            int o = buf * BK * LDB + r * LDB + bcol;
#pragma unroll
            for (int i = 0; i < 4; i++) { Bh[o + i] = hi[i]; Bl[o + i] = lo[i]; }
        }
    };

    loadG(0);
    storeS(0);
    __syncthreads();

    for (int kt = 0; kt < nk; ++kt) {
        int buf = kt & 1;
        if (kt + 1 < nk) loadG(kt + 1);   // LDG in flight during MMAs below

        const __nv_bfloat16* Ahb = Ah + buf * BM * LDA;
        const __nv_bfloat16* Alb = Al + buf * BM * LDA;
        const __nv_bfloat16* Bhb = Bh + buf * BK * LDB;
        const __nv_bfloat16* Blb = Bl + buf * BK * LDB;

        wmma::fragment<wmma::matrix_a, 16, 16, 16, __nv_bfloat16, wmma::row_major> ah[2], al[2];
        wmma::fragment<wmma::matrix_b, 16, 16, 16, __nv_bfloat16, wmma::row_major> bh[4], bl[4];
#pragma unroll
        for (int i = 0; i < 2; i++) {
            wmma::load_matrix_sync(ah[i], Ahb + (warp_m * 32 + i * 16) * LDA, LDA);
            wmma::load_matrix_sync(al[i], Alb + (warp_m * 32 + i * 16) * LDA, LDA);
        }
#pragma unroll
        for (int j = 0; j < 4; j++) {
            wmma::load_matrix_sync(bh[j], Bhb + warp_n * 64 + j * 16, LDB);
            wmma::load_matrix_sync(bl[j], Blb + warp_n * 64 + j * 16, LDB);
        }
#pragma unroll
        for (int i = 0; i < 2; i++)
#pragma unroll
            for (int j = 0; j < 4; j++) {
                wmma::mma_sync(acc[i][j], ah[i], bh[j], acc[i][j]);
                wmma::mma_sync(acc[i][j], al[i], bh[j], acc[i][j]);
                wmma::mma_sync(acc[i][j], ah[i], bl[j], acc[i][j]);
            }

        if (kt + 1 < nk) storeS(buf ^ 1); // prefetched data -> other buffer
        __syncthreads();
    }

    // Epilogue: two N-halves through smem staging; fused bias + GRU math.
    const int col4 = (tid & 15) * 4;
    const int r0   = tid >> 4;
#pragma unroll
    for (int half = 0; half < 2; ++half) {
        if (warp_n == half) {
#pragma unroll
            for (int i = 0; i < 2; i++)
#pragma unroll
                for (int j = 0; j < 4; j++)
                    wmma::store_matrix_sync(stage + (warp_m * 32 + i * 16) * LDS + j * 16,
                                            acc[i][j], LDS, wmma::mem_row_major);
        }
        __syncthreads();
#pragma unroll
        for (int rr = 0; rr < 8; ++rr) {
            int r = r0 + rr * 16;
            int m = bm0 + r;
            if (m < M) {
                float4 v = *(float4*)(stage + r * LDS + col4);
                int n = bn0 + half * 64 + col4;
                if (bias) {
                    v.x += bias[n + 0]; v.y += bias[n + 1];
                    v.z += bias[n + 2]; v.w += bias[n + 3];
                }
                if (epi == EPI_NONE) {
                    *(float4*)(C + (size_t)m * N + n) = v;
                } else if (epi == EPI_GATES) {
                    // n < 256: rh = sigmoid(v) * h ; n >= 256: u = sigmoid(v)
                    float s[4] = { v.x, v.y, v.z, v.w };
#pragma unroll
                    for (int q = 0; q < 4; q++) s[q] = 1.f / (1.f + expf(-s[q]));
                    if (n < 256) {
                        float4 hh = *(const float4*)(aux_h + (size_t)m * 256 + n);
                        float4 o;
                        o.x = s[0] * hh.x; o.y = s[1] * hh.y;
                        o.z = s[2] * hh.z; o.w = s[3] * hh.w;
                        *(float4*)(aux_rh + (size_t)m * 256 + n) = o;
                    } else {
                        float4 o; o.x = s[0]; o.y = s[1]; o.z = s[2]; o.w = s[3];
                        *(float4*)(aux_u + (size_t)m * 256 + (n - 256)) = o;
                    }
                } else {  // EPI_HOUT: h = u*h + (1-u)*tanh(v)
                    float4 uu = *(const float4*)(aux_u + (size_t)m * 256 + n);
                    float4 hh = *(const float4*)(aux_h + (size_t)m * 256 + n);
                    float4 o;
                    o.x = uu.x * hh.x + (1.f - uu.x) * tanhf(v.x);
                    o.y = uu.y * hh.y + (1.f - uu.y) * tanhf(v.y);
                    o.z = uu.z * hh.z + (1.f - uu.z) * tanhf(v.z);
                    o.w = uu.w * hh.w + (1.f - uu.w) * tanhf(v.w);
                    *(float4*)(aux_h + (size_t)m * 256 + n) = o;
                }
            }
        }
        __syncthreads();
    }
}

// ---------------- transform-first edge aggregation ----------------
// msg[tgt] += T[src, e-block];  msg[src] += T[tgt, (4+e)-block]
__global__ void scatter_kernel(const int* __restrict__ adj,
                               const float* __restrict__ T, float* __restrict__ msg)
{
    int unit = blockIdx.x * 4 + (threadIdx.x >> 6);
    if (unit >= NE * NM) return;
    int e = unit / NM;
    int m = unit - e * NM;
    int lane = threadIdx.x & 63;
    const int* ap = adj + ((size_t)e * NM + m) * 2;
    int src = __ldg(ap + 0);
    int tgt = __ldg(ap + 1);
    float4 a = *(const float4*)(T + (size_t)src * 2048 + e * 256 + lane * 4);
    float* d0 = msg + (size_t)tgt * NH + lane * 4;
    asm volatile("red.global.add.v4.f32 [%0], {%1,%2,%3,%4};"
                 :: "l"(d0), "f"(a.x), "f"(a.y), "f"(a.z), "f"(a.w) : "memory");
    float4 b = *(const float4*)(T + (size_t)tgt * 2048 + (4 + e) * 256 + lane * 4);
    float* d1 = msg + (size_t)src * NH + lane * 4;
    asm volatile("red.global.add.v4.f32 [%0], {%1,%2,%3,%4};"
                 :: "l"(d1), "f"(b.x), "f"(b.y), "f"(b.z), "f"(b.w) : "memory");
}

// ---------------- embedding: emb[v] = [label_e(128) | max_t type_e(128)] ----
__global__ void embed_kernel(const int* __restrict__ lab_ids, const int* __restrict__ typ_ids,
                             const float* __restrict__ typ_mask,
                             const float* __restrict__ lab_tab, const float* __restrict__ typ_tab,
                             float* __restrict__ emb)
{
    int v = blockIdx.x;
    int f = threadIdx.x;
    float val;
    if (f < 128) {
        val = lab_tab[(size_t)__ldg(&lab_ids[v]) * 128 + f];
    } else {
        int ff = f - 128;
        float mx = -3.4e38f;
        for (int t = 0; t < NT; ++t) {
            int ti = __ldg(&typ_ids[v * NT + t]);
            float mk = __ldg(&typ_mask[v * NT + t]);
            float e = typ_tab[(size_t)ti * 128 + ff] + (1.0f - mk) * (-BIGNEG);
            mx = fmaxf(mx, e);
        }
        val = mx;
    }
    emb[(size_t)v * 256 + f] = val;
}

// ---------------- host ----------------
static void* symaddr(const void* sym)
{
    void* p = nullptr;
    cudaGetSymbolAddress(&p, sym);
    return p;
}

static void launch_gemm(const float* const* partp, const int* partld, int nparts,
                        const float* B, float* C, const float* bias, int M, int N,
                        int bgroup, int epi, float* ah, float* arh, float* au)
{
    AParts ap;
    for (int i = 0; i < 8; ++i) {
        ap.p[i]  = (i < nparts) ? partp[i]  : nullptr;
        ap.ld[i] = (i < nparts) ? partld[i] : 0;
    }
    int K = nparts * 256;
    dim3 grid(N / 128, (M + 127) / 128);
    gemm_bf16x3<<<grid, 256>>>(ap, B, C, bias, M, N, K, bgroup, epi, ah, arh, au);
}

extern "C" void kernel_launch(void* const* d_in, const int* in_sizes, int n_in,
                              void* d_out, int out_size)
{
    const int*   lab_ids  = (const int*)  d_in[0];
    const int*   typ_ids  = (const int*)  d_in[1];
    const float* typ_mask = (const float*)d_in[2];
    const int*   adj      = (const int*)  d_in[3];
    const float* lab_tab  = (const float*)d_in[4];
    const float* typ_tab  = (const float*)d_in[5];
    const float* w_init   = (const float*)d_in[6];
    const float* edge_w   = (const float*)d_in[7];
    const float *wg[4], *bg[4], *wc[4], *bc[4];
    for (int l = 0; l < 4; ++l) {
        wg[l] = (const float*)d_in[8 + 4 * l];
        bg[l] = (const float*)d_in[9 + 4 * l];
        wc[l] = (const float*)d_in[10 + 4 * l];
        bc[l] = (const float*)d_in[11 + 4 * l];
    }

    float* h    = (float*)symaddr(g_h);
    float* s0   = (float*)symaddr(g_s0);
    float* s1   = (float*)symaddr(g_s1);
    float* msg  = (float*)symaddr(g_msg);
    float* rh   = (float*)symaddr(g_rh);
    float* u    = (float*)symaddr(g_u);
    float* emb  = (float*)symaddr(g_emb);
    float* T    = (float*)symaddr(g_T);

    const int steps[4] = {3, 1, 3, 1};
    const size_t VH_BYTES = (size_t)NV * NH * sizeof(float);

    // ---- embed + init projection ----
    embed_kernel<<<NV, 256>>>(lab_ids, typ_ids, typ_mask, lab_tab, typ_tab, emb);
    {
        const float* pp[1] = { emb }; int pl[1] = { 256 };
        launch_gemm(pp, pl, 1, w_init, h, nullptr, NV, 256, 0, EPI_NONE,
                    nullptr, nullptr, nullptr);
    }
    cudaMemcpyAsync(s0, h, VH_BYTES, cudaMemcpyDeviceToDevice, 0);

    for (int l = 0; l < 4; ++l) {
        for (int st = 0; st < steps[l]; ++st) {
            // ---- T = h @ edge_w[l] (grouped B, N=2048) ----
            {
                const float* pp[1] = { h }; int pl[1] = { 256 };
                launch_gemm(pp, pl, 1, edge_w + (size_t)l * 8 * NH * NH,
                            T, nullptr, NV, 2048, 1, EPI_NONE,
                            nullptr, nullptr, nullptr);
            }
            // ---- msg = scatter-add of T rows (L2-resident atomics) ----
            cudaMemsetAsync(msg, 0, VH_BYTES, 0);
            scatter_kernel<<<(NE * NM + 3) / 4, 256>>>(adj, T, msg);

            // ---- parts: x = [res..., msg] ----
            const float* px[4]; int nx;
            if (l == 0 || l == 2) { px[0] = msg; nx = 1; }
            else if (l == 1)      { px[0] = s0; px[1] = msg; nx = 2; }
            else                  { px[0] = s0; px[1] = s1; px[2] = msg; nx = 3; }

            // ---- gates: sigmoid([x,h]@wg + bg) -> rh, u (fused epilogue) ----
            {
                const float* pp[4]; int pl[4];
                for (int i = 0; i < nx; ++i) { pp[i] = px[i]; pl[i] = 256; }
                pp[nx] = h; pl[nx] = 256;
                launch_gemm(pp, pl, nx + 1, wg[l], nullptr, bg[l], NV, 512, 0,
                            EPI_GATES, h, rh, u);
            }

            // ---- h = u*h + (1-u)*tanh([x,rh]@wc + bc) (fused epilogue) ----
            {
                const float* pp[4]; int pl[4];
                for (int i = 0; i < nx; ++i) { pp[i] = px[i]; pl[i] = 256; }
                pp[nx] = rh; pl[nx] = 256;
                launch_gemm(pp, pl, nx + 1, wc[l], nullptr, bc[l], NV, 256, 0,
                            EPI_HOUT, h, nullptr, u);
            }
        }
        if (l == 0) cudaMemcpyAsync(s1, h, VH_BYTES, cudaMemcpyDeviceToDevice, 0);
    }

    cudaMemcpyAsync(d_out, h, VH_BYTES, cudaMemcpyDeviceToDevice, 0);
}